// round 15
// baseline (speedup 1.0000x reference)
#include <cuda_runtime.h>
#include <cuda_bf16.h>
#include <math.h>
#include <stdint.h>

#define T_DIM   64
#define B_DIM   512
#define D_DIM   768
#define H_DIM   12
#define HD_DIM  64
#define M_ROWS  (T_DIM * B_DIM)    /* 32768 */
#define QKV_N   (3 * D_DIM)        /* 2304  */

/* Scratch (device globals; no allocation allowed in kernel_launch) */
__device__ __nv_bfloat16  g_qkv16[M_ROWS * QKV_N];
__device__ __nv_bfloat16  g_a16[M_ROWS * D_DIM];
__device__ __nv_bfloat16  g_ctx16[M_ROWS * D_DIM];
__device__ float          g_out[M_ROWS * D_DIM];
__device__ __nv_bfloat16  g_wi16[QKV_N * D_DIM];
__device__ __nv_bfloat16  g_wo16[D_DIM * D_DIM];
__device__ float          g_invn[T_DIM * B_DIM];
__device__ float          g_mvec[T_DIM * D_DIM];

/* ================= PTX helpers ================= */
__device__ __forceinline__ uint32_t bf16x2(float lo, float hi) {
    uint32_t r;
    asm("cvt.rn.bf16x2.f32 %0, %1, %2;" : "=r"(r) : "f"(hi), "f"(lo));
    return r;
}
__device__ __forceinline__ void mma_bf16(float* c, const uint32_t* a,
                                         const uint32_t* b) {
    asm volatile(
        "mma.sync.aligned.m16n8k16.row.col.f32.bf16.bf16.f32 "
        "{%0,%1,%2,%3}, {%4,%5,%6,%7}, {%8,%9}, {%0,%1,%2,%3};\n"
        : "+f"(c[0]), "+f"(c[1]), "+f"(c[2]), "+f"(c[3])
        : "r"(a[0]), "r"(a[1]), "r"(a[2]), "r"(a[3]),
          "r"(b[0]), "r"(b[1]));
}
__device__ __forceinline__ void ldsm_x4(uint32_t* r, uint32_t addr) {
    asm volatile("ldmatrix.sync.aligned.m8n8.x4.shared.b16 {%0,%1,%2,%3}, [%4];"
                 : "=r"(r[0]), "=r"(r[1]), "=r"(r[2]), "=r"(r[3])
                 : "r"(addr));
}
__device__ __forceinline__ void ldsm_x4_t(uint32_t* r, uint32_t addr) {
    asm volatile("ldmatrix.sync.aligned.m8n8.x4.trans.shared.b16 {%0,%1,%2,%3}, [%4];"
                 : "=r"(r[0]), "=r"(r[1]), "=r"(r[2]), "=r"(r[3])
                 : "r"(addr));
}
__device__ __forceinline__ void cp_async16(uint32_t saddr, const void* g) {
    asm volatile("cp.async.cg.shared.global [%0], [%1], 16;\n"
                 :: "r"(saddr), "l"(g));
}
__device__ __forceinline__ void cp_commit() {
    asm volatile("cp.async.commit_group;\n");
}
template <int N> __device__ __forceinline__ void cp_wait() {
    asm volatile("cp.async.wait_group %0;\n" :: "n"(N));
}
__device__ __forceinline__ uint32_t smem_u32(const void* p) {
    return (uint32_t)__cvta_generic_to_shared(p);
}

/* ------------------------------------------------------------------ */
/* fp32 -> bf16 conversion                                             */
/* ------------------------------------------------------------------ */
__global__ void conv_bf16_kernel(const float* __restrict__ src,
                                 __nv_bfloat16* __restrict__ dst, int n)
{
    int i = (blockIdx.x * blockDim.x + threadIdx.x) * 4;
    if (i < n) {
        float4 v = *(const float4*)(src + i);
        uint2 p;
        p.x = bf16x2(v.x, v.y);
        p.y = bf16x2(v.z, v.w);
        *(uint2*)(dst + i) = p;
    }
}

/* ================================================================== */
/* bf16 GEMM: 128x256x64 tile, 512 threads / 16 warps (4m x 4n),       */
/* warp tile 32x64, ldmatrix + 3-stage cp.async, 12 epochs total.      */
/* C[M,N] = A[M,K] @ Bw[N,K]^T + bias[N]; OT = float or bf16 output.   */
/* smem rows: 64 bf16 (128B) + 16B pad = 144B -> conflict-free LDSM.   */
/* ================================================================== */
#define XBM 128
#define XBN 256
#define XBK 64
#define ROWB 144
#define A_BYTES (XBM * ROWB)            /* 18432 */
#define B_BYTES (XBN * ROWB)            /* 36864 */
#define STAGE_B (A_BYTES + B_BYTES)     /* 55296 */
#define XSMEM   (3 * STAGE_B)           /* 165888 */

template <typename OT>
__global__ __launch_bounds__(512, 1) void gemm_ldsm_kernel(
    const __nv_bfloat16* __restrict__ A, const __nv_bfloat16* __restrict__ Bw,
    const float* __restrict__ bias, OT* __restrict__ C,
    int M, int N, int K)
{
    extern __shared__ char dsm[];
    const uint32_t sb = smem_u32(dsm);

    const int tid  = threadIdx.x;
    const int warp = tid >> 5;
    const int lane = tid & 31;
    const int wm0  = (warp >> 2) * 32;     /* 0,32,64,96 */
    const int wn0  = (warp & 3) * 64;      /* 0..192     */
    const int bm   = blockIdx.y * XBM;
    const int bn   = blockIdx.x * XBN;

    /* A loader: 128 rows x 8 chunks of 16B -> 2 consecutive per thread */
    const int ar = tid >> 2;
    const int ac = (tid & 3) * 2;
    const __nv_bfloat16* Ag = A + (size_t)(bm + ar) * K + ac * 8;
    const uint32_t sA = sb + ar * ROWB + ac * 16;
    /* B loader: 256 rows x 8 chunks -> 4 consecutive per thread */
    const int br = tid >> 1;
    const int bc = (tid & 1) * 4;
    const __nv_bfloat16* Bg = Bw + (size_t)(bn + br) * K + bc * 8;
    const uint32_t sB = sb + A_BYTES + br * ROWB + bc * 16;

#define XLOAD(st, k0)                                                       \
    do {                                                                    \
        uint32_t o = (uint32_t)(st) * STAGE_B;                              \
        cp_async16(sA + o,      Ag + (k0));                                 \
        cp_async16(sA + o + 16, Ag + (k0) + 8);                             \
        cp_async16(sB + o,      Bg + (k0));                                 \
        cp_async16(sB + o + 16, Bg + (k0) + 8);                             \
        cp_async16(sB + o + 32, Bg + (k0) + 16);                            \
        cp_async16(sB + o + 48, Bg + (k0) + 24);                            \
    } while (0)

    float acc[2][8][4];
#pragma unroll
    for (int mt = 0; mt < 2; mt++)
#pragma unroll
        for (int nt = 0; nt < 8; nt++)
#pragma unroll
            for (int i = 0; i < 4; i++) acc[mt][nt][i] = 0.f;

    XLOAD(0, 0);    cp_commit();
    XLOAD(1, XBK);  cp_commit();

    const uint32_t aRow = (uint32_t)(wm0 + (lane & 15)) * ROWB
                        + ((lane >> 4) * 16);
    const uint32_t bRow = (uint32_t)(wn0 + ((lane >> 4) << 3) + (lane & 7)) * ROWB
                        + (((lane >> 3) & 1) * 16);

    const int NT = K / XBK;   /* 12 */
    for (int it = 0; it < NT; it++) {
        cp_wait<1>();
        __syncthreads();

        if (it + 2 < NT) XLOAD((it + 2) % 3, (it + 2) * XBK);
        cp_commit();

        const uint32_t ab = sb + (uint32_t)(it % 3) * STAGE_B;
        const uint32_t bb = ab + A_BYTES;

#pragma unroll
        for (int ks = 0; ks < 4; ks++) {
            uint32_t af[2][4], bf[4][4];
#pragma unroll
            for (int mt = 0; mt < 2; mt++)
                ldsm_x4(af[mt], ab + aRow + mt * (16 * ROWB) + ks * 32);
#pragma unroll
            for (int np = 0; np < 4; np++)
                ldsm_x4(bf[np], bb + bRow + np * (16 * ROWB) + ks * 32);
#pragma unroll
            for (int mt = 0; mt < 2; mt++) {
#pragma unroll
                for (int np = 0; np < 4; np++) {
                    mma_bf16(acc[mt][2 * np],     af[mt], &bf[np][0]);
                    mma_bf16(acc[mt][2 * np + 1], af[mt], &bf[np][2]);
                }
            }
        }
    }
#undef XLOAD

    const int erow = bm + wm0 + (lane >> 2);
    const int ecol = bn + wn0 + (lane & 3) * 2;
#pragma unroll
    for (int mt = 0; mt < 2; mt++) {
#pragma unroll
        for (int nt = 0; nt < 8; nt++) {
            int row = erow + mt * 16;
            int col = ecol + nt * 8;
            float b0 = bias[col], b1 = bias[col + 1];
            float v0 = acc[mt][nt][0] + b0, v1 = acc[mt][nt][1] + b1;
            float v2 = acc[mt][nt][2] + b0, v3 = acc[mt][nt][3] + b1;
            if (sizeof(OT) == 2) {
                *(uint32_t*)((__nv_bfloat16*)C + (size_t)row * N + col) =
                    bf16x2(v0, v1);
                *(uint32_t*)((__nv_bfloat16*)C + (size_t)(row + 8) * N + col) =
                    bf16x2(v2, v3);
            } else {
                *(float2*)((float*)C + (size_t)row * N + col) =
                    make_float2(v0, v1);
                *(float2*)((float*)C + (size_t)(row + 8) * N + col) =
                    make_float2(v2, v3);
            }
        }
    }
}

/* ================================================================== */
/* bf16 FA-style attention over B per (t,h)  (unchanged).              */
/* ================================================================== */
#define ARB 144
#define AQ_BYTES (128 * ARB)
#define AK_BYTES (64 * ARB)
#define ATTN_SMEM (AQ_BYTES + 2 * AK_BYTES)

__global__ __launch_bounds__(256, 2) void attn_bf16_kernel(
    const __nv_bfloat16* __restrict__ qkv, __nv_bfloat16* __restrict__ ctx)
{
    extern __shared__ char asmem[];
    const uint32_t Qs = smem_u32(asmem);
    const uint32_t Ks = Qs + AQ_BYTES;
    const uint32_t Vs = Ks + AK_BYTES;

    const int tid  = threadIdx.x;
    const int warp = tid >> 5;
    const int lane = tid & 31;
    const int g    = lane >> 2;
    const int tg   = lane & 3;
    const int qt   = blockIdx.x;
    const int h    = blockIdx.y;
    const int t    = blockIdx.z;

    const __nv_bfloat16* base = qkv + (size_t)t * B_DIM * QKV_N;
    const int qrow0 = qt * 128;
    const int qr    = warp * 16;

#pragma unroll
    for (int i = 0; i < 4; i++) {
        int f = i * 256 + tid;
        int r = f >> 3, c = f & 7;
        uint4 v = *(const uint4*)(base + (size_t)(qrow0 + r) * QKV_N
                                  + h * HD_DIM + c * 8);
        *(uint4*)(asmem + r * ARB + c * 16) = v;
    }
    __syncthreads();

    uint32_t qa[4][4];
    {
        uint32_t qaddr = Qs + (uint32_t)(qr + (lane & 7) + ((lane >> 3) & 1) * 8) * ARB
                       + ((lane >> 4) * 16);
#pragma unroll
        for (int ks = 0; ks < 4; ks++) ldsm_x4(qa[ks], qaddr + ks * 32);
    }

    float cacc[8][4];
#pragma unroll
    for (int nt = 0; nt < 8; nt++)
#pragma unroll
        for (int i = 0; i < 4; i++) cacc[nt][i] = 0.f;
    float l0 = 0.f, l1 = 0.f;

    const uint32_t kaddr = Ks + (uint32_t)(((lane >> 4) << 3) + (lane & 7)) * ARB
                         + (((lane >> 3) & 1) * 16);
    const uint32_t vaddr = Vs + (uint32_t)(lane & 15) * ARB + ((lane >> 4) * 16);

    for (int kt0 = 0; kt0 < B_DIM; kt0 += 64) {
        __syncthreads();
#pragma unroll
        for (int i = 0; i < 2; i++) {
            int f = i * 256 + tid;
            int r = f >> 3, c = f & 7;
            uint4 kv = *(const uint4*)(base + (size_t)(kt0 + r) * QKV_N
                                       + D_DIM + h * HD_DIM + c * 8);
            uint4 vv = *(const uint4*)(base + (size_t)(kt0 + r) * QKV_N
                                       + 2 * D_DIM + h * HD_DIM + c * 8);
            *(uint4*)(asmem + AQ_BYTES + r * ARB + c * 16) = kv;
            *(uint4*)(asmem + AQ_BYTES + AK_BYTES + r * ARB + c * 16) = vv;
        }
        __syncthreads();

        float sacc[8][4];
#pragma unroll
        for (int nt = 0; nt < 8; nt++)
#pragma unroll
            for (int i = 0; i < 4; i++) sacc[nt][i] = 0.f;

#pragma unroll
        for (int ks = 0; ks < 4; ks++) {
#pragma unroll
            for (int ntp = 0; ntp < 4; ntp++) {
                uint32_t kb[4];
                ldsm_x4(kb, kaddr + ntp * (16 * ARB) + ks * 32);
                mma_bf16(sacc[2 * ntp],     qa[ks], &kb[0]);
                mma_bf16(sacc[2 * ntp + 1], qa[ks], &kb[2]);
            }
        }

        uint32_t pp[8][2];
#pragma unroll
        for (int nt = 0; nt < 8; nt++) {
            float e0 = __expf(sacc[nt][0] * 0.125f);
            float e1 = __expf(sacc[nt][1] * 0.125f);
            float e2 = __expf(sacc[nt][2] * 0.125f);
            float e3 = __expf(sacc[nt][3] * 0.125f);
            l0 += e0 + e1;
            l1 += e2 + e3;
            pp[nt][0] = bf16x2(e0, e1);
            pp[nt][1] = bf16x2(e2, e3);
        }

#pragma unroll
        for (int ks = 0; ks < 4; ks++) {
            uint32_t pa[4] = {pp[2 * ks][0], pp[2 * ks][1],
                              pp[2 * ks + 1][0], pp[2 * ks + 1][1]};
#pragma unroll
            for (int hp = 0; hp < 4; hp++) {
                uint32_t vb[4];
                ldsm_x4_t(vb, vaddr + ks * (16 * ARB) + hp * 32);
                mma_bf16(cacc[2 * hp],     pa, &vb[0]);
                mma_bf16(cacc[2 * hp + 1], pa, &vb[2]);
            }
        }
    }

    l0 += __shfl_xor_sync(0xffffffffu, l0, 1);
    l0 += __shfl_xor_sync(0xffffffffu, l0, 2);
    l1 += __shfl_xor_sync(0xffffffffu, l1, 1);
    l1 += __shfl_xor_sync(0xffffffffu, l1, 2);
    const float inv0 = 1.f / l0;
    const float inv1 = 1.f / l1;

    const int row0 = t * B_DIM + qrow0 + qr + g;
#pragma unroll
    for (int nt = 0; nt < 8; nt++) {
        int col = h * HD_DIM + nt * 8 + 2 * tg;
        *(uint32_t*)(ctx + (size_t)row0 * D_DIM + col) =
            bf16x2(cacc[nt][0] * inv0, cacc[nt][1] * inv0);
        *(uint32_t*)(ctx + (size_t)(row0 + 8) * D_DIM + col) =
            bf16x2(cacc[nt][2] * inv1, cacc[nt][3] * inv1);
    }
}

/* ------------------------------------------------------------------ */
/* adj pipeline (3-stage, high occupancy)                             */
/* ------------------------------------------------------------------ */
__global__ __launch_bounds__(256) void adj_norm_kernel(
    const float* __restrict__ outm, float* __restrict__ invn)
{
    const int t    = blockIdx.y;
    const int tid  = threadIdx.x;
    const int lane = tid & 31;
    const int warp = tid >> 5;
    const float* O = outm + (size_t)t * B_DIM * D_DIM;

#pragma unroll
    for (int rr = 0; rr < 16; rr++) {
        int b = blockIdx.x * 128 + rr * 8 + warp;
        const float* row = O + (size_t)b * D_DIM;
        float ss = 0.f;
#pragma unroll
        for (int i = 0; i < 6; i++) {
            float4 v = *(const float4*)(row + lane * 4 + i * 128);
            ss += v.x * v.x + v.y * v.y + v.z * v.z + v.w * v.w;
        }
#pragma unroll
        for (int off = 16; off; off >>= 1)
            ss += __shfl_xor_sync(0xffffffffu, ss, off);
        if (lane == 0) invn[t * B_DIM + b] = 1.f / fmaxf(sqrtf(ss), 1e-8f);
    }
}

__global__ __launch_bounds__(128) void adj_mean_kernel(
    const float* __restrict__ outm, const float* __restrict__ invn,
    float* __restrict__ mvec)
{
    __shared__ float sinv[B_DIM];
    const int t   = blockIdx.y;
    const int tid = threadIdx.x;
    const int d   = blockIdx.x * 128 + tid;
    const float* O = outm + (size_t)t * B_DIM * D_DIM + d;

    for (int i = tid; i < B_DIM; i += 128) sinv[i] = invn[t * B_DIM + i];
    __syncthreads();

    float s = 0.f;
#pragma unroll 4
    for (int b = 0; b < B_DIM; b++)
        s += O[(size_t)b * D_DIM] * sinv[b];
    mvec[t * D_DIM + d] = s * (1.f / (float)B_DIM);
}

__global__ __launch_bounds__(256) void adj_dot_kernel(
    const float* __restrict__ outm, const float* __restrict__ invn,
    const float* __restrict__ mvec, float* __restrict__ adj)
{
    __shared__ float mv[D_DIM];
    const int t    = blockIdx.y;
    const int tid  = threadIdx.x;
    const int lane = tid & 31;
    const int warp = tid >> 5;
    const float* O = outm + (size_t)t * B_DIM * D_DIM;

    for (int i = tid; i < D_DIM; i += 256) mv[i] = mvec[t * D_DIM + i];
    __syncthreads();

#pragma unroll
    for (int rr = 0; rr < 16; rr++) {
        int b = blockIdx.x * 128 + rr * 8 + warp;
        const float* row = O + (size_t)b * D_DIM;
        float s = 0.f;
#pragma unroll
        for (int i = 0; i < 6; i++) {
            int d = lane * 4 + i * 128;
            float4 v = *(const float4*)(row + d);
            s += v.x * mv[d] + v.y * mv[d + 1]
               + v.z * mv[d + 2] + v.w * mv[d + 3];
        }
#pragma unroll
        for (int off = 16; off; off >>= 1)
            s += __shfl_xor_sync(0xffffffffu, s, off);
        if (lane == 0) adj[t * B_DIM + b] = s * invn[t * B_DIM + b];
    }
}

/* ------------------------------------------------------------------ */
extern "C" void kernel_launch(void* const* d_in, const int* in_sizes, int n_in,
                              void* d_out, int out_size)
{
    const float* node = (const float*)d_in[0];
    const float* wi   = (const float*)d_in[1];
    const float* bi   = (const float*)d_in[2];
    const float* wo   = (const float*)d_in[3];
    const float* bo   = (const float*)d_in[4];

    float *outm, *invn, *mvec;
    __nv_bfloat16 *qkv16, *a16, *ctx16, *wi16, *wo16;
    cudaGetSymbolAddress((void**)&qkv16, g_qkv16);
    cudaGetSymbolAddress((void**)&outm,  g_out);
    cudaGetSymbolAddress((void**)&a16,   g_a16);
    cudaGetSymbolAddress((void**)&ctx16, g_ctx16);
    cudaGetSymbolAddress((void**)&wi16,  g_wi16);
    cudaGetSymbolAddress((void**)&wo16,  g_wo16);
    cudaGetSymbolAddress((void**)&invn,  g_invn);
    cudaGetSymbolAddress((void**)&mvec,  g_mvec);

    cudaFuncSetAttribute(attn_bf16_kernel,
                         cudaFuncAttributeMaxDynamicSharedMemorySize,
                         ATTN_SMEM);
    cudaFuncSetAttribute(gemm_ldsm_kernel<__nv_bfloat16>,
                         cudaFuncAttributeMaxDynamicSharedMemorySize, XSMEM);
    cudaFuncSetAttribute(gemm_ldsm_kernel<float>,
                         cudaFuncAttributeMaxDynamicSharedMemorySize, XSMEM);

    /* 0) bf16 conversions */
    conv_bf16_kernel<<<(M_ROWS * D_DIM / 4 + 255) / 256, 256>>>(
        node, a16, M_ROWS * D_DIM);
    conv_bf16_kernel<<<(QKV_N * D_DIM / 4 + 255) / 256, 256>>>(
        wi, wi16, QKV_N * D_DIM);
    conv_bf16_kernel<<<(D_DIM * D_DIM / 4 + 255) / 256, 256>>>(
        wo, wo16, D_DIM * D_DIM);

    /* 1) QKV projection -> bf16 (512-thread, k64-epoch GEMM) */
    gemm_ldsm_kernel<__nv_bfloat16>
        <<<dim3(QKV_N / XBN, M_ROWS / XBM), 512, XSMEM>>>(
        a16, wi16, bi, qkv16, M_ROWS, QKV_N, D_DIM);

    /* 2) attention (all-bf16 tensor path) */
    attn_bf16_kernel<<<dim3(4, H_DIM, T_DIM), 256, ATTN_SMEM>>>(qkv16, ctx16);

    /* 3) output projection -> fp32 */
    gemm_ldsm_kernel<float>
        <<<dim3(D_DIM / XBN, M_ROWS / XBM), 512, XSMEM>>>(
        ctx16, wo16, bo, outm, M_ROWS, D_DIM, D_DIM);

    /* 4) cosine-sim mean reduction */
    adj_norm_kernel<<<dim3(4, T_DIM), 256>>>(outm, invn);
    adj_mean_kernel<<<dim3(6, T_DIM), 128>>>(outm, invn, mvec);
    adj_dot_kernel<<<dim3(4, T_DIM), 256>>>(outm, invn, mvec, (float*)d_out);
}

// round 16
// speedup vs baseline: 1.1046x; 1.1046x over previous
#include <cuda_runtime.h>
#include <cuda_bf16.h>
#include <math.h>
#include <stdint.h>

#define T_DIM   64
#define B_DIM   512
#define D_DIM   768
#define H_DIM   12
#define HD_DIM  64
#define M_ROWS  (T_DIM * B_DIM)    /* 32768 */
#define QKV_N   (3 * D_DIM)        /* 2304  */

/* Scratch (device globals; no allocation allowed in kernel_launch) */
__device__ __nv_bfloat16  g_qkv16[M_ROWS * QKV_N];
__device__ __nv_bfloat16  g_a16[M_ROWS * D_DIM];
__device__ __nv_bfloat16  g_ctx16[M_ROWS * D_DIM];
__device__ __nv_bfloat16  g_out16[M_ROWS * D_DIM];
__device__ __nv_bfloat16  g_wi16[QKV_N * D_DIM];
__device__ __nv_bfloat16  g_wo16[D_DIM * D_DIM];
__device__ float          g_invn[T_DIM * B_DIM];
__device__ float          g_mvec[T_DIM * D_DIM];

/* ================= PTX helpers ================= */
__device__ __forceinline__ uint32_t bf16x2(float lo, float hi) {
    uint32_t r;
    asm("cvt.rn.bf16x2.f32 %0, %1, %2;" : "=r"(r) : "f"(hi), "f"(lo));
    return r;
}
__device__ __forceinline__ void mma_bf16(float* c, const uint32_t* a,
                                         const uint32_t* b) {
    asm volatile(
        "mma.sync.aligned.m16n8k16.row.col.f32.bf16.bf16.f32 "
        "{%0,%1,%2,%3}, {%4,%5,%6,%7}, {%8,%9}, {%0,%1,%2,%3};\n"
        : "+f"(c[0]), "+f"(c[1]), "+f"(c[2]), "+f"(c[3])
        : "r"(a[0]), "r"(a[1]), "r"(a[2]), "r"(a[3]),
          "r"(b[0]), "r"(b[1]));
}
__device__ __forceinline__ void ldsm_x4(uint32_t* r, uint32_t addr) {
    asm volatile("ldmatrix.sync.aligned.m8n8.x4.shared.b16 {%0,%1,%2,%3}, [%4];"
                 : "=r"(r[0]), "=r"(r[1]), "=r"(r[2]), "=r"(r[3])
                 : "r"(addr));
}
__device__ __forceinline__ void ldsm_x4_t(uint32_t* r, uint32_t addr) {
    asm volatile("ldmatrix.sync.aligned.m8n8.x4.trans.shared.b16 {%0,%1,%2,%3}, [%4];"
                 : "=r"(r[0]), "=r"(r[1]), "=r"(r[2]), "=r"(r[3])
                 : "r"(addr));
}
__device__ __forceinline__ void cp_async16(uint32_t saddr, const void* g) {
    asm volatile("cp.async.cg.shared.global [%0], [%1], 16;\n"
                 :: "r"(saddr), "l"(g));
}
__device__ __forceinline__ void cp_commit() {
    asm volatile("cp.async.commit_group;\n");
}
template <int N> __device__ __forceinline__ void cp_wait() {
    asm volatile("cp.async.wait_group %0;\n" :: "n"(N));
}
__device__ __forceinline__ uint32_t smem_u32(const void* p) {
    return (uint32_t)__cvta_generic_to_shared(p);
}

/* ------------------------------------------------------------------ */
/* fp32 -> bf16 conversion                                             */
/* ------------------------------------------------------------------ */
__global__ void conv_bf16_kernel(const float* __restrict__ src,
                                 __nv_bfloat16* __restrict__ dst, int n)
{
    int i = (blockIdx.x * blockDim.x + threadIdx.x) * 4;
    if (i < n) {
        float4 v = *(const float4*)(src + i);
        uint2 p;
        p.x = bf16x2(v.x, v.y);
        p.y = bf16x2(v.z, v.w);
        *(uint2*)(dst + i) = p;
    }
}

/* ================================================================== */
/* bf16 GEMM (R14 config — measured best): 128x256x32, 512 threads,    */
/* 16 warps (4m x 4n), warp tile 32x64, ldmatrix + 3-stage cp.async.   */
/* C[M,N] = A[M,K] @ Bw[N,K]^T + bias[N]; bf16 output.                 */
/* ================================================================== */
#define XBM 128
#define XBN 256
#define XBK 32
#define ROWB 80
#define A_BYTES (XBM * ROWB)            /* 10240 */
#define B_BYTES (XBN * ROWB)            /* 20480 */
#define STAGE_B (A_BYTES + B_BYTES)     /* 30720 */
#define XSMEM   (3 * STAGE_B)           /* 92160 */

__global__ __launch_bounds__(512, 1) void gemm_ldsm_kernel(
    const __nv_bfloat16* __restrict__ A, const __nv_bfloat16* __restrict__ Bw,
    const float* __restrict__ bias, __nv_bfloat16* __restrict__ C,
    int M, int N, int K)
{
    extern __shared__ char dsm[];
    const uint32_t sb = smem_u32(dsm);

    const int tid  = threadIdx.x;
    const int warp = tid >> 5;
    const int lane = tid & 31;
    const int wm0  = (warp >> 2) * 32;
    const int wn0  = (warp & 3) * 64;
    const int bm   = blockIdx.y * XBM;
    const int bn   = blockIdx.x * XBN;

    /* A loader: 128 rows x 4 chunks of 16B, one per thread */
    const int ar = tid >> 2;
    const int ac = tid & 3;
    const __nv_bfloat16* Ag = A + (size_t)(bm + ar) * K + ac * 8;
    const uint32_t sA = sb + ar * ROWB + ac * 16;
    /* B loader: 256 rows x 4 chunks, two consecutive per thread */
    const int br = tid >> 1;
    const int bc = (tid & 1) * 2;
    const __nv_bfloat16* Bg = Bw + (size_t)(bn + br) * K + bc * 8;
    const uint32_t sB = sb + A_BYTES + br * ROWB + bc * 16;

#define XLOAD(st, k0)                                                       \
    do {                                                                    \
        uint32_t o = (uint32_t)(st) * STAGE_B;                              \
        cp_async16(sA + o,      Ag + (k0));                                 \
        cp_async16(sB + o,      Bg + (k0));                                 \
        cp_async16(sB + o + 16, Bg + (k0) + 8);                             \
    } while (0)

    float acc[2][8][4];
#pragma unroll
    for (int mt = 0; mt < 2; mt++)
#pragma unroll
        for (int nt = 0; nt < 8; nt++)
#pragma unroll
            for (int i = 0; i < 4; i++) acc[mt][nt][i] = 0.f;

    XLOAD(0, 0);    cp_commit();
    XLOAD(1, XBK);  cp_commit();

    const uint32_t aRow = (uint32_t)(wm0 + (lane & 15)) * ROWB
                        + ((lane >> 4) * 16);
    const uint32_t bRow = (uint32_t)(wn0 + ((lane >> 4) << 3) + (lane & 7)) * ROWB
                        + (((lane >> 3) & 1) * 16);

    const int NT = K / XBK;
    for (int it = 0; it < NT; it++) {
        cp_wait<1>();
        __syncthreads();

        if (it + 2 < NT) XLOAD((it + 2) % 3, (it + 2) * XBK);
        cp_commit();

        const uint32_t ab = sb + (uint32_t)(it % 3) * STAGE_B;
        const uint32_t bb = ab + A_BYTES;

#pragma unroll
        for (int ks = 0; ks < 2; ks++) {
            uint32_t af[2][4], bf[4][4];
#pragma unroll
            for (int mt = 0; mt < 2; mt++)
                ldsm_x4(af[mt], ab + aRow + mt * (16 * ROWB) + ks * 32);
#pragma unroll
            for (int np = 0; np < 4; np++)
                ldsm_x4(bf[np], bb + bRow + np * (16 * ROWB) + ks * 32);
#pragma unroll
            for (int mt = 0; mt < 2; mt++) {
#pragma unroll
                for (int np = 0; np < 4; np++) {
                    mma_bf16(acc[mt][2 * np],     af[mt], &bf[np][0]);
                    mma_bf16(acc[mt][2 * np + 1], af[mt], &bf[np][2]);
                }
            }
        }
    }
#undef XLOAD

    const int erow = bm + wm0 + (lane >> 2);
    const int ecol = bn + wn0 + (lane & 3) * 2;
#pragma unroll
    for (int mt = 0; mt < 2; mt++) {
#pragma unroll
        for (int nt = 0; nt < 8; nt++) {
            int row = erow + mt * 16;
            int col = ecol + nt * 8;
            float b0 = bias[col], b1 = bias[col + 1];
            *(uint32_t*)(C + (size_t)row * N + col) =
                bf16x2(acc[mt][nt][0] + b0, acc[mt][nt][1] + b1);
            *(uint32_t*)(C + (size_t)(row + 8) * N + col) =
                bf16x2(acc[mt][nt][2] + b0, acc[mt][nt][3] + b1);
        }
    }
}

/* ================================================================== */
/* bf16 FA-style attention over B per (t,h)  (unchanged).              */
/* ================================================================== */
#define ARB 144
#define AQ_BYTES (128 * ARB)
#define AK_BYTES (64 * ARB)
#define ATTN_SMEM (AQ_BYTES + 2 * AK_BYTES)

__global__ __launch_bounds__(256, 2) void attn_bf16_kernel(
    const __nv_bfloat16* __restrict__ qkv, __nv_bfloat16* __restrict__ ctx)
{
    extern __shared__ char asmem[];
    const uint32_t Qs = smem_u32(asmem);
    const uint32_t Ks = Qs + AQ_BYTES;
    const uint32_t Vs = Ks + AK_BYTES;

    const int tid  = threadIdx.x;
    const int warp = tid >> 5;
    const int lane = tid & 31;
    const int g    = lane >> 2;
    const int tg   = lane & 3;
    const int qt   = blockIdx.x;
    const int h    = blockIdx.y;
    const int t    = blockIdx.z;

    const __nv_bfloat16* base = qkv + (size_t)t * B_DIM * QKV_N;
    const int qrow0 = qt * 128;
    const int qr    = warp * 16;

#pragma unroll
    for (int i = 0; i < 4; i++) {
        int f = i * 256 + tid;
        int r = f >> 3, c = f & 7;
        uint4 v = *(const uint4*)(base + (size_t)(qrow0 + r) * QKV_N
                                  + h * HD_DIM + c * 8);
        *(uint4*)(asmem + r * ARB + c * 16) = v;
    }
    __syncthreads();

    uint32_t qa[4][4];
    {
        uint32_t qaddr = Qs + (uint32_t)(qr + (lane & 7) + ((lane >> 3) & 1) * 8) * ARB
                       + ((lane >> 4) * 16);
#pragma unroll
        for (int ks = 0; ks < 4; ks++) ldsm_x4(qa[ks], qaddr + ks * 32);
    }

    float cacc[8][4];
#pragma unroll
    for (int nt = 0; nt < 8; nt++)
#pragma unroll
        for (int i = 0; i < 4; i++) cacc[nt][i] = 0.f;
    float l0 = 0.f, l1 = 0.f;

    const uint32_t kaddr = Ks + (uint32_t)(((lane >> 4) << 3) + (lane & 7)) * ARB
                         + (((lane >> 3) & 1) * 16);
    const uint32_t vaddr = Vs + (uint32_t)(lane & 15) * ARB + ((lane >> 4) * 16);

    for (int kt0 = 0; kt0 < B_DIM; kt0 += 64) {
        __syncthreads();
#pragma unroll
        for (int i = 0; i < 2; i++) {
            int f = i * 256 + tid;
            int r = f >> 3, c = f & 7;
            uint4 kv = *(const uint4*)(base + (size_t)(kt0 + r) * QKV_N
                                       + D_DIM + h * HD_DIM + c * 8);
            uint4 vv = *(const uint4*)(base + (size_t)(kt0 + r) * QKV_N
                                       + 2 * D_DIM + h * HD_DIM + c * 8);
            *(uint4*)(asmem + AQ_BYTES + r * ARB + c * 16) = kv;
            *(uint4*)(asmem + AQ_BYTES + AK_BYTES + r * ARB + c * 16) = vv;
        }
        __syncthreads();

        float sacc[8][4];
#pragma unroll
        for (int nt = 0; nt < 8; nt++)
#pragma unroll
            for (int i = 0; i < 4; i++) sacc[nt][i] = 0.f;

#pragma unroll
        for (int ks = 0; ks < 4; ks++) {
#pragma unroll
            for (int ntp = 0; ntp < 4; ntp++) {
                uint32_t kb[4];
                ldsm_x4(kb, kaddr + ntp * (16 * ARB) + ks * 32);
                mma_bf16(sacc[2 * ntp],     qa[ks], &kb[0]);
                mma_bf16(sacc[2 * ntp + 1], qa[ks], &kb[2]);
            }
        }

        uint32_t pp[8][2];
#pragma unroll
        for (int nt = 0; nt < 8; nt++) {
            float e0 = __expf(sacc[nt][0] * 0.125f);
            float e1 = __expf(sacc[nt][1] * 0.125f);
            float e2 = __expf(sacc[nt][2] * 0.125f);
            float e3 = __expf(sacc[nt][3] * 0.125f);
            l0 += e0 + e1;
            l1 += e2 + e3;
            pp[nt][0] = bf16x2(e0, e1);
            pp[nt][1] = bf16x2(e2, e3);
        }

#pragma unroll
        for (int ks = 0; ks < 4; ks++) {
            uint32_t pa[4] = {pp[2 * ks][0], pp[2 * ks][1],
                              pp[2 * ks + 1][0], pp[2 * ks + 1][1]};
#pragma unroll
            for (int hp = 0; hp < 4; hp++) {
                uint32_t vb[4];
                ldsm_x4_t(vb, vaddr + ks * (16 * ARB) + hp * 32);
                mma_bf16(cacc[2 * hp],     pa, &vb[0]);
                mma_bf16(cacc[2 * hp + 1], pa, &vb[2]);
            }
        }
    }

    l0 += __shfl_xor_sync(0xffffffffu, l0, 1);
    l0 += __shfl_xor_sync(0xffffffffu, l0, 2);
    l1 += __shfl_xor_sync(0xffffffffu, l1, 1);
    l1 += __shfl_xor_sync(0xffffffffu, l1, 2);
    const float inv0 = 1.f / l0;
    const float inv1 = 1.f / l1;

    const int row0 = t * B_DIM + qrow0 + qr + g;
#pragma unroll
    for (int nt = 0; nt < 8; nt++) {
        int col = h * HD_DIM + nt * 8 + 2 * tg;
        *(uint32_t*)(ctx + (size_t)row0 * D_DIM + col) =
            bf16x2(cacc[nt][0] * inv0, cacc[nt][1] * inv0);
        *(uint32_t*)(ctx + (size_t)(row0 + 8) * D_DIM + col) =
            bf16x2(cacc[nt][2] * inv1, cacc[nt][3] * inv1);
    }
}

/* ------------------------------------------------------------------ */
/* adj pipeline on bf16 out (fp32 accumulation).                      */
/* ------------------------------------------------------------------ */
__device__ __forceinline__ float dot8_bf16(uint4 v, const float* m) {
    const __nv_bfloat162* p = (const __nv_bfloat162*)&v;
    float s = 0.f;
#pragma unroll
    for (int j = 0; j < 4; j++) {
        float2 f = __bfloat1622float2(p[j]);
        s += f.x * m[2 * j] + f.y * m[2 * j + 1];
    }
    return s;
}

__global__ __launch_bounds__(256) void adj_norm_kernel(
    const __nv_bfloat16* __restrict__ outm, float* __restrict__ invn)
{
    const int t    = blockIdx.y;
    const int tid  = threadIdx.x;
    const int lane = tid & 31;
    const int warp = tid >> 5;
    const __nv_bfloat16* O = outm + (size_t)t * B_DIM * D_DIM;

#pragma unroll
    for (int rr = 0; rr < 16; rr++) {
        int b = blockIdx.x * 128 + rr * 8 + warp;
        const __nv_bfloat16* row = O + (size_t)b * D_DIM;
        float ss = 0.f;
#pragma unroll
        for (int i = 0; i < 3; i++) {
            uint4 v = *(const uint4*)(row + lane * 8 + i * 256);
            const __nv_bfloat162* p = (const __nv_bfloat162*)&v;
#pragma unroll
            for (int j = 0; j < 4; j++) {
                float2 f = __bfloat1622float2(p[j]);
                ss += f.x * f.x + f.y * f.y;
            }
        }
#pragma unroll
        for (int off = 16; off; off >>= 1)
            ss += __shfl_xor_sync(0xffffffffu, ss, off);
        if (lane == 0) invn[t * B_DIM + b] = 1.f / fmaxf(sqrtf(ss), 1e-8f);
    }
}

__global__ __launch_bounds__(128) void adj_mean_kernel(
    const __nv_bfloat16* __restrict__ outm, const float* __restrict__ invn,
    float* __restrict__ mvec)
{
    __shared__ float sinv[B_DIM];
    const int t   = blockIdx.y;
    const int tid = threadIdx.x;
    const int d   = blockIdx.x * 128 + tid;
    const __nv_bfloat16* O = outm + (size_t)t * B_DIM * D_DIM + d;

    for (int i = tid; i < B_DIM; i += 128) sinv[i] = invn[t * B_DIM + i];
    __syncthreads();

    float s = 0.f;
#pragma unroll 4
    for (int b = 0; b < B_DIM; b++)
        s += __bfloat162float(O[(size_t)b * D_DIM]) * sinv[b];
    mvec[t * D_DIM + d] = s * (1.f / (float)B_DIM);
}

__global__ __launch_bounds__(256) void adj_dot_kernel(
    const __nv_bfloat16* __restrict__ outm, const float* __restrict__ invn,
    const float* __restrict__ mvec, float* __restrict__ adj)
{
    __shared__ float mv[D_DIM];
    const int t    = blockIdx.y;
    const int tid  = threadIdx.x;
    const int lane = tid & 31;
    const int warp = tid >> 5;
    const __nv_bfloat16* O = outm + (size_t)t * B_DIM * D_DIM;

    for (int i = tid; i < D_DIM; i += 256) mv[i] = mvec[t * D_DIM + i];
    __syncthreads();

#pragma unroll
    for (int rr = 0; rr < 16; rr++) {
        int b = blockIdx.x * 128 + rr * 8 + warp;
        const __nv_bfloat16* row = O + (size_t)b * D_DIM;
        float s = 0.f;
#pragma unroll
        for (int i = 0; i < 3; i++) {
            int d = lane * 8 + i * 256;
            uint4 v = *(const uint4*)(row + d);
            s += dot8_bf16(v, &mv[d]);
        }
#pragma unroll
        for (int off = 16; off; off >>= 1)
            s += __shfl_xor_sync(0xffffffffu, s, off);
        if (lane == 0) adj[t * B_DIM + b] = s * invn[t * B_DIM + b];
    }
}

/* ------------------------------------------------------------------ */
extern "C" void kernel_launch(void* const* d_in, const int* in_sizes, int n_in,
                              void* d_out, int out_size)
{
    const float* node = (const float*)d_in[0];
    const float* wi   = (const float*)d_in[1];
    const float* bi   = (const float*)d_in[2];
    const float* wo   = (const float*)d_in[3];
    const float* bo   = (const float*)d_in[4];

    float *invn, *mvec;
    __nv_bfloat16 *qkv16, *a16, *ctx16, *out16, *wi16, *wo16;
    cudaGetSymbolAddress((void**)&qkv16, g_qkv16);
    cudaGetSymbolAddress((void**)&out16, g_out16);
    cudaGetSymbolAddress((void**)&a16,   g_a16);
    cudaGetSymbolAddress((void**)&ctx16, g_ctx16);
    cudaGetSymbolAddress((void**)&wi16,  g_wi16);
    cudaGetSymbolAddress((void**)&wo16,  g_wo16);
    cudaGetSymbolAddress((void**)&invn,  g_invn);
    cudaGetSymbolAddress((void**)&mvec,  g_mvec);

    cudaFuncSetAttribute(attn_bf16_kernel,
                         cudaFuncAttributeMaxDynamicSharedMemorySize,
                         ATTN_SMEM);
    cudaFuncSetAttribute(gemm_ldsm_kernel,
                         cudaFuncAttributeMaxDynamicSharedMemorySize, XSMEM);

    /* 0) bf16 conversions */
    conv_bf16_kernel<<<(M_ROWS * D_DIM / 4 + 255) / 256, 256>>>(
        node, a16, M_ROWS * D_DIM);
    conv_bf16_kernel<<<(QKV_N * D_DIM / 4 + 255) / 256, 256>>>(
        wi, wi16, QKV_N * D_DIM);
    conv_bf16_kernel<<<(D_DIM * D_DIM / 4 + 255) / 256, 256>>>(
        wo, wo16, D_DIM * D_DIM);

    /* 1) QKV projection -> bf16 */
    gemm_ldsm_kernel<<<dim3(QKV_N / XBN, M_ROWS / XBM), 512, XSMEM>>>(
        a16, wi16, bi, qkv16, M_ROWS, QKV_N, D_DIM);

    /* 2) attention (all-bf16 tensor path) */
    attn_bf16_kernel<<<dim3(4, H_DIM, T_DIM), 256, ATTN_SMEM>>>(qkv16, ctx16);

    /* 3) output projection -> bf16 */
    gemm_ldsm_kernel<<<dim3(D_DIM / XBN, M_ROWS / XBM), 512, XSMEM>>>(
        ctx16, wo16, bo, out16, M_ROWS, D_DIM, D_DIM);

    /* 4) cosine-sim mean reduction (bf16 reads, fp32 math) */
    adj_norm_kernel<<<dim3(4, T_DIM), 256>>>(out16, invn);
    adj_mean_kernel<<<dim3(6, T_DIM), 128>>>(out16, invn, mvec);
    adj_dot_kernel<<<dim3(4, T_DIM), 256>>>(out16, invn, mvec, (float*)d_out);
}